// round 5
// baseline (speedup 1.0000x reference)
#include <cuda_runtime.h>
#include <cuda_fp16.h>
#include <cstdint>

#define DI __device__ __forceinline__

// ------------------------- problem sizes -------------------------
#define N_NODES_C 16384
#define N_EDGES_C 131072
#define N_GRAPHS_C 16
#define U_SZ_C 4096
#define U_RED_C 256
#define EDGE_H_C 1024
#define EDGE_OUT_C 512
#define NODE_H_C 512

// padded concat widths (multiples of 32 for BK)
// e_in layout : [u_r 0-255][x_row 256-264][x_col 265-273][ea 274][pad->287]
// n_in layout : [e 0-511][x_col 512-520][pad->543]
// o_in layout : [agg 0-511][u_r 512-767][x 768-776][pad->799]
#define K_EIN 288
#define K_NIN 544
#define K_OIN 800

// ------------------------- device scratch -------------------------
__device__ __half g_ein [(size_t)N_EDGES_C * K_EIN];
__device__ __half g_bufA[(size_t)N_EDGES_C * EDGE_H_C];
__device__ __half g_bufB[(size_t)N_EDGES_C * EDGE_H_C];
__device__ __half g_nin [(size_t)N_EDGES_C * K_NIN];
__device__ __half g_oin [(size_t)N_NODES_C * K_OIN];
__device__ __half g_h2  [(size_t)N_NODES_C * NODE_H_C];
__device__ float  g_ur  [N_GRAPHS_C * U_RED_C];

__device__ __half g_w0h  [K_EIN    * EDGE_H_C];
__device__ __half g_w1h  [EDGE_H_C * EDGE_H_C];
__device__ __half g_w2h  [EDGE_H_C * EDGE_H_C];
__device__ __half g_w3h  [EDGE_H_C * EDGE_H_C];
__device__ __half g_wfh  [EDGE_H_C * EDGE_OUT_C];
__device__ __half g_n1w0h[K_NIN    * NODE_H_C];
__device__ __half g_n1w1h[NODE_H_C * NODE_H_C];
__device__ __half g_n2w0h[K_OIN    * NODE_H_C];

__device__ int g_cnt[N_NODES_C];
__device__ int g_off[N_NODES_C + 1];
__device__ int g_cur[N_NODES_C];
__device__ int g_elist[N_EDGES_C];

// ------------------------- small helpers -------------------------
DI uint32_t smem_u32(const void* p) {
    return (uint32_t)__cvta_generic_to_shared(p);
}
DI void cp16(uint32_t dst, const void* src) {
    asm volatile("cp.async.cg.shared.global [%0], [%1], 16;\n" :: "r"(dst), "l"(src));
}
DI void cp_commit() { asm volatile("cp.async.commit_group;\n"); }
DI void cp_wait0()  { asm volatile("cp.async.wait_group 0;\n"); }

DI void ldm_x4(uint32_t addr, uint32_t& r0, uint32_t& r1, uint32_t& r2, uint32_t& r3) {
    asm volatile("ldmatrix.sync.aligned.m8n8.x4.shared.b16 {%0,%1,%2,%3}, [%4];\n"
                 : "=r"(r0), "=r"(r1), "=r"(r2), "=r"(r3) : "r"(addr));
}
DI void ldm_x4t(uint32_t addr, uint32_t& r0, uint32_t& r1, uint32_t& r2, uint32_t& r3) {
    asm volatile("ldmatrix.sync.aligned.m8n8.x4.trans.shared.b16 {%0,%1,%2,%3}, [%4];\n"
                 : "=r"(r0), "=r"(r1), "=r"(r2), "=r"(r3) : "r"(addr));
}
DI void mma16816(float* d, const uint32_t* a, const uint32_t* b) {
    asm volatile("mma.sync.aligned.m16n8k16.row.col.f32.f16.f16.f32 "
                 "{%0,%1,%2,%3}, {%4,%5,%6,%7}, {%8,%9}, {%0,%1,%2,%3};\n"
                 : "+f"(d[0]), "+f"(d[1]), "+f"(d[2]), "+f"(d[3])
                 : "r"(a[0]), "r"(a[1]), "r"(a[2]), "r"(a[3]),
                   "r"(b[0]), "r"(b[1]));
}

// --------------- weight pack: fp32 -> fp16, row permute + zero pad ---------------
struct Seg { int src0, dst0, n; };

__global__ void pack_weight(const float* __restrict__ src, __half* __restrict__ dst,
                            int N, int Kp, Seg a, Seg b, Seg c, Seg d) {
    int idx = blockIdx.x * blockDim.x + threadIdx.x;
    if (idx >= Kp * N) return;
    int r = idx / N, col = idx - r * N;
    float v = 0.f;
    if      (r >= a.dst0 && r < a.dst0 + a.n) v = src[(size_t)(a.src0 + r - a.dst0) * N + col];
    else if (r >= b.dst0 && r < b.dst0 + b.n) v = src[(size_t)(b.src0 + r - b.dst0) * N + col];
    else if (r >= c.dst0 && r < c.dst0 + c.n) v = src[(size_t)(c.src0 + r - c.dst0) * N + col];
    else if (r >= d.dst0 && r < d.dst0 + d.n) v = src[(size_t)(d.src0 + r - d.dst0) * N + col];
    dst[idx] = __float2half(v);
}

// --------------- dim reduction: u_r = u @ w_dr + b_dr (fp32, tiny) ---------------
// grid (16 graphs, 8 col-tiles), 256 threads = 8 k-groups x 32 cols.
__global__ void dimred_kernel(const float* __restrict__ u, const float* __restrict__ w,
                              const float* __restrict__ b) {
    __shared__ float red[8][32];
    int g = blockIdx.x, ct = blockIdx.y;
    int kg = threadIdx.x >> 5, cl = threadIdx.x & 31;
    int c = ct * 32 + cl;
    const float* up = u + (size_t)g * U_SZ_C + kg * 512;
    const float* wp = w + (size_t)(kg * 512) * U_RED_C + c;
    float s = 0.f;
    #pragma unroll 8
    for (int k = 0; k < 512; k++) s += up[k] * wp[(size_t)k * U_RED_C];
    red[kg][cl] = s;
    __syncthreads();
    if (kg == 0) {
        float t = b[c];
        #pragma unroll
        for (int i = 0; i < 8; i++) t += red[i][cl];
        g_ur[g * U_RED_C + c] = t;
    }
}

// --------------- build e_in (permuted layout), one warp per edge -----------------
__global__ void build_ein_kernel(const float* __restrict__ x, const float* __restrict__ ea,
                                 const int* __restrict__ ei, const int* __restrict__ batch) {
    int e = blockIdx.x * 8 + (threadIdx.x >> 5);
    int lane = threadIdx.x & 31;
    int r = ei[e], c = ei[N_EDGES_C + e];
    int g = batch[r];
    __half* dst = g_ein + (size_t)e * K_EIN;
    const float* ur = g_ur + g * U_RED_C;
    #pragma unroll
    for (int j = 0; j < 8; j++)
        dst[j * 32 + lane] = __float2half(ur[j * 32 + lane]);
    float v = 0.f;
    if (lane < 9)        v = x[(size_t)r * 9 + lane];
    else if (lane < 18)  v = x[(size_t)c * 9 + (lane - 9)];
    else if (lane == 18) v = ea[e];
    dst[256 + lane] = __float2half(v);   // covers cols 256..287 incl. zero pad
}

// write x[col] into n_in cols 512..520, zeros 521..543
__global__ void add_x_nin_kernel(const float* __restrict__ x, const int* __restrict__ ei) {
    int e = blockIdx.x * 8 + (threadIdx.x >> 5);
    int lane = threadIdx.x & 31;
    int c = ei[N_EDGES_C + e];
    float v = (lane < 9) ? x[(size_t)c * 9 + lane] : 0.f;
    g_nin[(size_t)e * K_NIN + 512 + lane] = __float2half(v);
}

// ------------------------- fp16 tensor-core GEMM ---------------------------------
// C[M,N](fp16) = act(A[M,K](fp16,row) @ B[K,N](fp16,row) + bias)
#define BM 128
#define BN 128
#define BKK 32
#define GT 256

template<bool RELU>
__global__ __launch_bounds__(GT)
void gemm_kernel(const __half* __restrict__ A, int lda,
                 const __half* __restrict__ B, int ldb,
                 const float* __restrict__ bias,
                 __half* __restrict__ C, int ldc, int K) {
    __shared__ alignas(16) __half As[2][BM][40];    // pad 32->40: conflict-free ldmatrix
    __shared__ alignas(16) __half Bs[2][BKK][136];  // pad 128->136

    const int tid  = threadIdx.x;
    const int lane = tid & 31, warp = tid >> 5;
    const int wm = warp & 1;    // 2 warps along M -> 64 rows each
    const int wn = warp >> 1;   // 4 warps along N -> 32 cols each
    const int bm = blockIdx.y, bn = blockIdx.x;

    const __half* Ag = A + (size_t)bm * BM * lda;
    const __half* Bg = B + (size_t)bn * BN;

    float acc[4][4][4];
    #pragma unroll
    for (int i = 0; i < 4; i++)
        #pragma unroll
        for (int j = 0; j < 4; j++)
            #pragma unroll
            for (int k = 0; k < 4; k++) acc[i][j][k] = 0.f;

    const int KT = K / BKK;

    auto load = [&](int kt, int st) {
        #pragma unroll
        for (int i = 0; i < 2; i++) {
            int ch = tid + i * GT;                 // 512 x 16B chunks for A tile
            int r = ch >> 2, cc = (ch & 3) << 3;
            cp16(smem_u32(&As[st][r][cc]), Ag + (size_t)r * lda + kt * BKK + cc);
        }
        #pragma unroll
        for (int i = 0; i < 2; i++) {
            int ch = tid + i * GT;                 // 512 x 16B chunks for B tile
            int r = ch >> 4, cc = (ch & 15) << 3;
            cp16(smem_u32(&Bs[st][r][cc]), Bg + (size_t)(kt * BKK + r) * ldb + cc);
        }
        cp_commit();
    };

    load(0, 0);
    for (int kt = 0; kt < KT; kt++) {
        cp_wait0();
        __syncthreads();
        if (kt + 1 < KT) load(kt + 1, (kt + 1) & 1);
        const int st = kt & 1;

        #pragma unroll
        for (int ks = 0; ks < 2; ks++) {
            uint32_t afr[4][4];
            {
                int row = wm * 64 + (lane & 15);
                int col = ks * 16 + (lane >> 4) * 8;
                #pragma unroll
                for (int mi = 0; mi < 4; mi++)
                    ldm_x4(smem_u32(&As[st][row + mi * 16][col]),
                           afr[mi][0], afr[mi][1], afr[mi][2], afr[mi][3]);
            }
            uint32_t bfr[4][2];
            {
                int row = ks * 16 + ((lane >> 3) & 1) * 8 + (lane & 7);
                #pragma unroll
                for (int p = 0; p < 2; p++) {
                    int col = wn * 32 + p * 16 + (lane >> 4) * 8;
                    uint32_t r0, r1, r2, r3;
                    ldm_x4t(smem_u32(&Bs[st][row][col]), r0, r1, r2, r3);
                    bfr[2 * p][0] = r0;     bfr[2 * p][1] = r1;
                    bfr[2 * p + 1][0] = r2; bfr[2 * p + 1][1] = r3;
                }
            }
            #pragma unroll
            for (int mi = 0; mi < 4; mi++)
                #pragma unroll
                for (int nj = 0; nj < 4; nj++)
                    mma16816(acc[mi][nj], afr[mi], bfr[nj]);
        }
        __syncthreads();
    }

    // epilogue: bias + (relu) + fp16 store
    int row0 = bm * BM + wm * 64;
    int col0 = bn * BN + wn * 32;
    #pragma unroll
    for (int mi = 0; mi < 4; mi++) {
        #pragma unroll
        for (int nj = 0; nj < 4; nj++) {
            int c = col0 + nj * 8 + (lane & 3) * 2;
            float b0 = bias[c], b1 = bias[c + 1];
            #pragma unroll
            for (int h = 0; h < 2; h++) {
                int r = row0 + mi * 16 + (lane >> 2) + h * 8;
                float f0 = acc[mi][nj][2 * h] + b0;
                float f1 = acc[mi][nj][2 * h + 1] + b1;
                if (RELU) { f0 = fmaxf(f0, 0.f); f1 = fmaxf(f1, 0.f); }
                *reinterpret_cast<__half2*>(C + (size_t)r * ldc + c) = __floats2half2_rn(f0, f1);
            }
        }
    }
}

// --------------- scatter-mean: CSR build + gather reduce -------------------------
__global__ void zero_cnt_kernel() {
    int i = blockIdx.x * blockDim.x + threadIdx.x;
    if (i < N_NODES_C) { g_cnt[i] = 0; g_cur[i] = 0; }
}
__global__ void count_kernel(const int* __restrict__ ei) {
    int e = blockIdx.x * blockDim.x + threadIdx.x;
    if (e < N_EDGES_C) atomicAdd(&g_cnt[ei[e]], 1);
}
__global__ void scan_kernel() {   // single block, 1024 threads x 16 elems
    __shared__ int ws[32];
    int t = threadIdx.x;
    int base = t * 16;
    int v[16]; int s = 0;
    #pragma unroll
    for (int i = 0; i < 16; i++) { v[i] = s; s += g_cnt[base + i]; }
    int lane = t & 31, w = t >> 5;
    int x = s;
    #pragma unroll
    for (int o = 1; o < 32; o <<= 1) { int y = __shfl_up_sync(~0u, x, o); if (lane >= o) x += y; }
    if (lane == 31) ws[w] = x;
    __syncthreads();
    if (w == 0) {
        int y = ws[lane];
        #pragma unroll
        for (int o = 1; o < 32; o <<= 1) { int z = __shfl_up_sync(~0u, y, o); if (lane >= o) y += z; }
        ws[lane] = y;
    }
    __syncthreads();
    int pre = (x - s) + (w > 0 ? ws[w - 1] : 0);
    #pragma unroll
    for (int i = 0; i < 16; i++) g_off[base + i] = pre + v[i];
    if (t == 1023) g_off[N_NODES_C] = pre + s;
}
__global__ void fill_kernel(const int* __restrict__ ei) {
    int e = blockIdx.x * blockDim.x + threadIdx.x;
    if (e < N_EDGES_C) {
        int r = ei[e];
        int p = g_off[r] + atomicAdd(&g_cur[r], 1);
        g_elist[p] = e;
    }
}
// block per node: mean over its edges of h_n (g_bufB [E,512] fp16); fuse o_in build
__global__ void node_reduce_kernel(const float* __restrict__ x, const int* __restrict__ batch) {
    int n = blockIdx.x;
    int t = threadIdx.x;  // 128
    int deg = g_cnt[n], start = g_off[n];
    float acc0 = 0.f, acc1 = 0.f, acc2 = 0.f, acc3 = 0.f;
    for (int i = 0; i < deg; i++) {
        int e = g_elist[start + i];
        const __half* hr = g_bufB + (size_t)e * NODE_H_C;
        acc0 += __half2float(hr[t]);
        acc1 += __half2float(hr[t + 128]);
        acc2 += __half2float(hr[t + 256]);
        acc3 += __half2float(hr[t + 384]);
    }
    float inv = 1.f / (float)(deg > 0 ? deg : 1);
    __half* dst = g_oin + (size_t)n * K_OIN;
    dst[t]       = __float2half(acc0 * inv);
    dst[t + 128] = __float2half(acc1 * inv);
    dst[t + 256] = __float2half(acc2 * inv);
    dst[t + 384] = __float2half(acc3 * inv);
    int g = batch[n];
    dst[512 + t] = __float2half(g_ur[g * U_RED_C + t]);
    dst[640 + t] = __float2half(g_ur[g * U_RED_C + 128 + t]);
    if (t < 32) dst[768 + t] = __float2half(t < 9 ? x[(size_t)n * 9 + t] : 0.f);
}

// --------------- final dot: out[n] = h2[n,:] . n2_w1 + b --------------------------
__global__ void final_kernel(const float* __restrict__ w, const float* __restrict__ b,
                             float* __restrict__ out) {
    int n = blockIdx.x * 8 + (threadIdx.x >> 5);
    int lane = threadIdx.x & 31;
    const __half* h = g_h2 + (size_t)n * NODE_H_C;
    float s = 0.f;
    #pragma unroll
    for (int j = 0; j < 16; j++) {
        int c = lane + j * 32;
        s += __half2float(h[c]) * w[c];
    }
    #pragma unroll
    for (int o = 16; o > 0; o >>= 1) s += __shfl_xor_sync(~0u, s, o);
    if (lane == 0) out[n] = s + b[0];
}

// ------------------------- host launcher -----------------------------------------
extern "C" void kernel_launch(void* const* d_in, const int* in_sizes, int n_in,
                              void* d_out, int out_size) {
    (void)in_sizes; (void)n_in; (void)out_size;
    const float* x      = (const float*)d_in[0];
    const float* ea     = (const float*)d_in[1];
    const float* u      = (const float*)d_in[2];
    const int*   ei     = (const int*)d_in[3];
    const int*   batch  = (const int*)d_in[4];
    const float* w_dr   = (const float*)d_in[5];
    const float* b_dr   = (const float*)d_in[6];
    const float* e_w0   = (const float*)d_in[7];
    const float* e_b0   = (const float*)d_in[8];
    const float* e_w1   = (const float*)d_in[9];
    const float* e_b1   = (const float*)d_in[10];
    const float* e_w2   = (const float*)d_in[11];
    const float* e_b2   = (const float*)d_in[12];
    const float* e_w3   = (const float*)d_in[13];
    const float* e_b3   = (const float*)d_in[14];
    const float* e_wf   = (const float*)d_in[15];
    const float* e_bf   = (const float*)d_in[16];
    const float* n1_w0  = (const float*)d_in[17];
    const float* n1_b0  = (const float*)d_in[18];
    const float* n1_w1  = (const float*)d_in[19];
    const float* n1_b1  = (const float*)d_in[20];
    const float* n2_w0  = (const float*)d_in[21];
    const float* n2_b0  = (const float*)d_in[22];
    const float* n2_w1  = (const float*)d_in[23];
    const float* n2_b1  = (const float*)d_in[24];
    float* out = (float*)d_out;

    __half *w0h, *w1h, *w2h, *w3h, *wfh, *n1w0h, *n1w1h, *n2w0h;
    __half *ein, *bufA, *bufB, *nin, *oin, *h2;
    cudaGetSymbolAddress((void**)&w0h,   g_w0h);
    cudaGetSymbolAddress((void**)&w1h,   g_w1h);
    cudaGetSymbolAddress((void**)&w2h,   g_w2h);
    cudaGetSymbolAddress((void**)&w3h,   g_w3h);
    cudaGetSymbolAddress((void**)&wfh,   g_wfh);
    cudaGetSymbolAddress((void**)&n1w0h, g_n1w0h);
    cudaGetSymbolAddress((void**)&n1w1h, g_n1w1h);
    cudaGetSymbolAddress((void**)&n2w0h, g_n2w0h);
    cudaGetSymbolAddress((void**)&ein,  g_ein);
    cudaGetSymbolAddress((void**)&bufA, g_bufA);
    cudaGetSymbolAddress((void**)&bufB, g_bufB);
    cudaGetSymbolAddress((void**)&nin,  g_nin);
    cudaGetSymbolAddress((void**)&oin,  g_oin);
    cudaGetSymbolAddress((void**)&h2,   g_h2);

    const Seg Z{0, 0, 0};
    auto gsz = [](int n) { return (n + 255) / 256; };

    // pack weights fp32->fp16 with row permutation matching our concat layouts
    pack_weight<<<gsz(K_EIN * 1024), 256>>>(e_w0, w0h, 1024, K_EIN,
        Seg{19, 0, 256}, Seg{0, 256, 9}, Seg{9, 265, 9}, Seg{18, 274, 1});
    pack_weight<<<gsz(1024 * 1024), 256>>>(e_w1, w1h, 1024, 1024, Seg{0, 0, 1024}, Z, Z, Z);
    pack_weight<<<gsz(1024 * 1024), 256>>>(e_w2, w2h, 1024, 1024, Seg{0, 0, 1024}, Z, Z, Z);
    pack_weight<<<gsz(1024 * 1024), 256>>>(e_w3, w3h, 1024, 1024, Seg{0, 0, 1024}, Z, Z, Z);
    pack_weight<<<gsz(1024 * 512),  256>>>(e_wf, wfh, 512, 1024, Seg{0, 0, 1024}, Z, Z, Z);
    pack_weight<<<gsz(K_NIN * 512), 256>>>(n1_w0, n1w0h, 512, K_NIN,
        Seg{9, 0, 512}, Seg{0, 512, 9}, Z, Z);
    pack_weight<<<gsz(512 * 512),   256>>>(n1_w1, n1w1h, 512, 512, Seg{0, 0, 512}, Z, Z, Z);
    pack_weight<<<gsz(K_OIN * 512), 256>>>(n2_w0, n2w0h, 512, K_OIN,
        Seg{9, 0, 512}, Seg{521, 512, 256}, Seg{0, 768, 9}, Z);

    // u dim reduction + edge input build
    dimred_kernel<<<dim3(16, 8), 256>>>(u, w_dr, b_dr);
    build_ein_kernel<<<N_EDGES_C / 8, 256>>>(x, ea, ei, batch);

    // edge MLP
    gemm_kernel<true ><<<dim3(8, N_EDGES_C / BM), GT>>>(ein,  K_EIN, w0h, 1024, e_b0, bufA, 1024, K_EIN);
    gemm_kernel<true ><<<dim3(8, N_EDGES_C / BM), GT>>>(bufA, 1024,  w1h, 1024, e_b1, bufB, 1024, 1024);
    gemm_kernel<true ><<<dim3(8, N_EDGES_C / BM), GT>>>(bufB, 1024,  w2h, 1024, e_b2, bufA, 1024, 1024);
    gemm_kernel<true ><<<dim3(8, N_EDGES_C / BM), GT>>>(bufA, 1024,  w3h, 1024, e_b3, bufB, 1024, 1024);
    gemm_kernel<false><<<dim3(4, N_EDGES_C / BM), GT>>>(bufB, 1024,  wfh,  512, e_bf, nin,  K_NIN, 1024);

    // node MLP 1 (inputs: [e 0-511][x_col 512-520])
    add_x_nin_kernel<<<N_EDGES_C / 8, 256>>>(x, ei);
    gemm_kernel<true ><<<dim3(4, N_EDGES_C / BM), GT>>>(nin,  K_NIN, n1w0h, 512, n1_b0, bufA, 512, K_NIN);
    gemm_kernel<true ><<<dim3(4, N_EDGES_C / BM), GT>>>(bufA, 512,   n1w1h, 512, n1_b1, bufB, 512, 512);

    // scatter-mean via CSR build, fused with o_in construction
    zero_cnt_kernel<<<N_NODES_C / 256, 256>>>();
    count_kernel<<<N_EDGES_C / 256, 256>>>(ei);
    scan_kernel<<<1, 1024>>>();
    fill_kernel<<<N_EDGES_C / 256, 256>>>(ei);
    node_reduce_kernel<<<N_NODES_C, 128>>>(x, batch);

    // node MLP 2 + final dot
    gemm_kernel<true ><<<dim3(4, N_NODES_C / BM), GT>>>(oin, K_OIN, n2w0h, 512, n2_b0, h2, 512, K_OIN);
    final_kernel<<<N_NODES_C / 8, 256>>>(n2_w1, n2_b1, out);
}